// round 16
// baseline (speedup 1.0000x reference)
#include <cuda_runtime.h>
#include <cuda_bf16.h>
#include <cstdint>

#define NN 8192
#define CC 256
#define EE 262144
#define HH 4

// ---- scratch (no allocation allowed -> __device__ globals) ----
__device__ int   g_cnt[NN];
__device__ int   g_off[NN + 1];
__device__ int   g_cur[NN];
__device__ int2  g_ebuf[EE];                     // {row, float_bits(val)} binned by col
__device__ float g_proj[NN * CC];
__device__ float g_local[NN * CC];
__device__ float g_pO[2 * NN * CC];              // split-K attention O partials (raw sums)
__device__ float g_pl[2 * HH * NN];              // split-K l partials
__device__ __nv_bfloat16 g_qbf[HH * NN * 64];    // pre-scaled by 0.125*log2(e)
__device__ __nv_bfloat16 g_kbf[HH * NN * 64];
__device__ __nv_bfloat16 g_vbf[HH * NN * 64];
__device__ __nv_bfloat16 g_ah[NN * CC];          // activation hi [M,K]
__device__ __nv_bfloat16 g_al[NN * CC];          // activation lo
__device__ __nv_bfloat16 g_bh[NN * CC];          // GCN-path activation hi
__device__ __nv_bfloat16 g_bl[NN * CC];          // GCN-path activation lo
__device__ __nv_bfloat16 g_wh[1536 * CC];        // in_w(768)|out_w(256)|fc_w(256)|w_localT(256)
__device__ __nv_bfloat16 g_wl[1536 * CC];

#define QS_CONST (0.125f * 1.44269504089f)

// ================= helpers =================
__device__ __forceinline__ uint32_t smem_u32(const void* p) {
    uint32_t a;
    asm("{ .reg .u64 t; cvta.to.shared.u64 t, %1; cvt.u32.u64 %0, t; }" : "=r"(a) : "l"(p));
    return a;
}
#define SWZ(o)   ((o) ^ (((o) >> 3) & 0x70))
#define SWZ64(o) ((o) ^ (((o) >> 3) & 0x30))

#define CP_ASYNC16(dst, src) asm volatile("cp.async.cg.shared.global [%0], [%1], 16;" :: "r"(dst), "l"(src))
#define CP_COMMIT()          asm volatile("cp.async.commit_group;" ::: "memory")
#define CP_WAIT1()           asm volatile("cp.async.wait_group 1;" ::: "memory")

__device__ __forceinline__ void ldm_x4(uint32_t* r, uint32_t addr) {
    asm volatile("ldmatrix.sync.aligned.m8n8.x4.shared.b16 {%0,%1,%2,%3}, [%4];"
        : "=r"(r[0]), "=r"(r[1]), "=r"(r[2]), "=r"(r[3]) : "r"(addr));
}
__device__ __forceinline__ void ldm_x4_t(uint32_t* r, uint32_t addr) {
    asm volatile("ldmatrix.sync.aligned.m8n8.x4.trans.shared.b16 {%0,%1,%2,%3}, [%4];"
        : "=r"(r[0]), "=r"(r[1]), "=r"(r[2]), "=r"(r[3]) : "r"(addr));
}
__device__ __forceinline__ void mma16816(float* c, const uint32_t* a, uint32_t b0, uint32_t b1) {
    asm volatile("mma.sync.aligned.m16n8k16.row.col.f32.bf16.bf16.f32 "
        "{%0,%1,%2,%3}, {%4,%5,%6,%7}, {%8,%9}, {%0,%1,%2,%3};"
        : "+f"(c[0]), "+f"(c[1]), "+f"(c[2]), "+f"(c[3])
        : "r"(a[0]), "r"(a[1]), "r"(a[2]), "r"(a[3]), "r"(b0), "r"(b1));
}
__device__ __forceinline__ uint32_t lm_addr(uint32_t base, int row0, int off0, int lane) {
    int m = lane >> 3;
    int row = row0 + (lane & 7) + ((m & 1) << 3);
    int off = off0 + ((m >> 1) << 4);
    return base + SWZ(row * 128 + off);
}
__device__ __forceinline__ uint32_t lm64(uint32_t base, int row0, int off0, int lane) {
    int m = lane >> 3;
    int row = row0 + (lane & 7) + ((m & 1) << 3);
    int off = off0 + ((m >> 1) << 4);
    return base + SWZ64(row * 64 + off);
}
__device__ __forceinline__ void store_split(__nv_bfloat16* ah, __nv_bfloat16* al,
                                            long long idx, float v0, float v1) {
    __nv_bfloat16 h0 = __float2bfloat16(v0), h1 = __float2bfloat16(v1);
    *reinterpret_cast<__nv_bfloat162*>(ah + idx) = __nv_bfloat162(h0, h1);
    *reinterpret_cast<__nv_bfloat162*>(al + idx) =
        __floats2bfloat162_rn(v0 - __bfloat162float(h0), v1 - __bfloat162float(h1));
}

// ---------------- GCN: deg / scan / bin / gather ----------------
__global__ void k_zero() {
    int i = blockIdx.x * blockDim.x + threadIdx.x;
    if (i < NN) g_cnt[i] = 0;
}

__global__ void k_deg(const int* __restrict__ adj) {
    int e = blockIdx.x * blockDim.x + threadIdx.x;
    if (e >= EE) return;
    unsigned col = (unsigned)adj[EE + e];
    if (col < NN) atomicAdd(&g_cnt[col], 1);
}

// single block, 1024 threads, 8 elems/thread; warp scan + cross-warp
__global__ void __launch_bounds__(1024) k_scan() {
    __shared__ int wsum[32];
    int t = threadIdx.x, lane = t & 31, w = t >> 5;
    int4 a = reinterpret_cast<const int4*>(g_cnt)[2 * t];
    int4 b = reinterpret_cast<const int4*>(g_cnt)[2 * t + 1];
    int v[8] = {a.x, a.y, a.z, a.w, b.x, b.y, b.z, b.w};
    int pre[8], s = 0;
    #pragma unroll
    for (int i = 0; i < 8; i++) { pre[i] = s; s += v[i]; }
    int inc = s;
    #pragma unroll
    for (int off = 1; off < 32; off <<= 1) {
        int n = __shfl_up_sync(0xffffffffu, inc, off);
        if (lane >= off) inc += n;
    }
    if (lane == 31) wsum[w] = inc;
    __syncthreads();
    if (w == 0) {
        int x = wsum[lane];
        #pragma unroll
        for (int off = 1; off < 32; off <<= 1) {
            int n = __shfl_up_sync(0xffffffffu, x, off);
            if (lane >= off) x += n;
        }
        wsum[lane] = x;
    }
    __syncthreads();
    int base = (w ? wsum[w - 1] : 0) + inc - s;
    int o[8];
    #pragma unroll
    for (int i = 0; i < 8; i++) o[i] = base + pre[i];
    reinterpret_cast<int4*>(g_off)[2 * t]     = make_int4(o[0], o[1], o[2], o[3]);
    reinterpret_cast<int4*>(g_off)[2 * t + 1] = make_int4(o[4], o[5], o[6], o[7]);
    reinterpret_cast<int4*>(g_cur)[2 * t]     = make_int4(o[0], o[1], o[2], o[3]);
    reinterpret_cast<int4*>(g_cur)[2 * t + 1] = make_int4(o[4], o[5], o[6], o[7]);
    if (t == 1023) g_off[NN] = base + s;
}

__global__ void k_bin(const int* __restrict__ adj) {
    int e = blockIdx.x * blockDim.x + threadIdx.x;
    if (e >= EE) return;
    unsigned row = (unsigned)adj[e];
    unsigned col = (unsigned)adj[EE + e];
    if (row >= NN || col >= NN) return;
    float p = (float)(g_cnt[col] * g_cnt[row]);
    float val = (p > 0.f) ? rsqrtf(p) : 0.f;
    int pos = atomicAdd(&g_cur[col], 1);
    g_ebuf[pos] = make_int2((int)row, __float_as_int(val));
}

// 4 nodes per block; 64 threads/node, 4 channels/thread -> split-bf16 g_bh/g_bl
__global__ void __launch_bounds__(256) k_gather(const float* __restrict__ x) {
    int n = blockIdx.x * 4 + (threadIdx.x >> 6);
    int c = (threadIdx.x & 63) * 4;
    int e = g_off[n], end = g_off[n + 1];
    float a0 = 0.f, a1 = 0.f, a2 = 0.f, a3 = 0.f;
    for (; e + 2 <= end; e += 2) {
        int2 ev0 = g_ebuf[e], ev1 = g_ebuf[e + 1];
        float v0 = __int_as_float(ev0.y), v1 = __int_as_float(ev1.y);
        float4 x0 = *reinterpret_cast<const float4*>(x + (long long)ev0.x * CC + c);
        float4 x1 = *reinterpret_cast<const float4*>(x + (long long)ev1.x * CC + c);
        a0 += x0.x * v0 + x1.x * v1;
        a1 += x0.y * v0 + x1.y * v1;
        a2 += x0.z * v0 + x1.z * v1;
        a3 += x0.w * v0 + x1.w * v1;
    }
    if (e < end) {
        int2 ev = g_ebuf[e];
        float v = __int_as_float(ev.y);
        float4 x0 = *reinterpret_cast<const float4*>(x + (long long)ev.x * CC + c);
        a0 += x0.x * v; a1 += x0.y * v; a2 += x0.z * v; a3 += x0.w * v;
    }
    long long idx = (long long)n * CC + c;
    store_split(g_bh, g_bl, idx, a0, a1);
    store_split(g_bh, g_bl, idx + 2, a2, a3);
}

// ---------------- split-bf16 weight / activation conversion ----------------
__global__ void __launch_bounds__(256) k_cvtw(
    const float* __restrict__ in_w, const float* __restrict__ out_w,
    const float* __restrict__ fc_w, const float* __restrict__ w_local)
{
    int i = blockIdx.x * 256 + threadIdx.x;
    if (i >= 1536 * 256) return;
    int row = i >> 8, k = i & 255;
    float v;
    if (row < 768)       v = in_w[i];
    else if (row < 1024) v = out_w[(row - 768) * 256 + k];
    else if (row < 1280) v = fc_w[(row - 1024) * 256 + k];
    else                 v = w_local[k * 256 + (row - 1280)];   // transpose
    __nv_bfloat16 h = __float2bfloat16(v);
    g_wh[i] = h;
    g_wl[i] = __float2bfloat16(v - __bfloat162float(h));
}

__global__ void __launch_bounds__(256) k_cvta(const float* __restrict__ src) {
    int t = blockIdx.x * 256 + threadIdx.x;
    float4 v = reinterpret_cast<const float4*>(src)[t];
    long long idx = (long long)t * 4;
    store_split(g_ah, g_al, idx, v.x, v.y);
    store_split(g_ah, g_al, idx + 2, v.z, v.w);
}

// ---------------- tensor-core bf16 GEMM ----------------
// EPI 0: fp32 C + bias.  EPI 1: bf16 qkv (q scaled) straight to g_qbf/kbf/vbf.
// TERMS 3: Ah*Bh + Ah*Bl + Al*Bh.  TERMS 1: Ah*Bh.
// ASRC 0: A from Ah/Al (bf16, cp.async).  ASRC 1: A = split-K combine of g_pO/g_pl
//         (fp32 loads + in-register combine + bf16 STS); Ah/Al args unused.
template <int EPI, int TERMS, int ASRC>
__global__ void __launch_bounds__(256, 2) k_gemm_tc(
    const __nv_bfloat16* __restrict__ Ah, const __nv_bfloat16* __restrict__ Al,
    const __nv_bfloat16* __restrict__ Bh, const __nv_bfloat16* __restrict__ Bl,
    const float* __restrict__ bias, float* __restrict__ C, int N, int K)
{
    __shared__ __align__(128) char sm[49152];
    int tid = threadIdx.x, w = tid >> 5, lane = tid & 31;
    int n0 = blockIdx.x * 64, m0 = blockIdx.y * 128;
    int mw = (w >> 1) * 32, nw = (w & 1) * 32;

    auto copy_chunk = [&](int ck) {
        int k0 = ck * 32;
        char* buf = sm + (ck & 1) * 24576;
        if (ASRC == 0) {
            #pragma unroll
            for (int i = 0; i < 2; i++) {
                int c = tid + i * 256;
                int r = c >> 2, s = c & 3;
                uint32_t off = SWZ64(r * 64 + s * 16);
                CP_ASYNC16(smem_u32(buf + off), Ah + (long long)(m0 + r) * K + k0 + s * 8);
                if (TERMS == 3)
                    CP_ASYNC16(smem_u32(buf + 8192 + off), Al + (long long)(m0 + r) * K + k0 + s * 8);
            }
        } else {
            // split-K combine: 8 fp32 from each half + per-(row,head) l -> 8 bf16
            #pragma unroll
            for (int i = 0; i < 2; i++) {
                int c = tid + i * 256;
                int r = c >> 2, s = c & 3;
                int col = k0 + s * 8;
                int h = col >> 6;
                int grow = m0 + r;
                long long idx = (long long)grow * CC + col;
                float4 a0 = *reinterpret_cast<const float4*>(g_pO + idx);
                float4 a1 = *reinterpret_cast<const float4*>(g_pO + idx + 4);
                float4 b0 = *reinterpret_cast<const float4*>(g_pO + (long long)NN * CC + idx);
                float4 b1 = *reinterpret_cast<const float4*>(g_pO + (long long)NN * CC + idx + 4);
                float l = g_pl[h * NN + grow] + g_pl[HH * NN + h * NN + grow];
                float inv = 1.0f / l;
                uint32_t p0, p1, p2, p3;
                asm("cvt.rn.satfinite.bf16x2.f32 %0, %1, %2;" : "=r"(p0) : "f"((a0.y + b0.y) * inv), "f"((a0.x + b0.x) * inv));
                asm("cvt.rn.satfinite.bf16x2.f32 %0, %1, %2;" : "=r"(p1) : "f"((a0.w + b0.w) * inv), "f"((a0.z + b0.z) * inv));
                asm("cvt.rn.satfinite.bf16x2.f32 %0, %1, %2;" : "=r"(p2) : "f"((a1.y + b1.y) * inv), "f"((a1.x + b1.x) * inv));
                asm("cvt.rn.satfinite.bf16x2.f32 %0, %1, %2;" : "=r"(p3) : "f"((a1.w + b1.w) * inv), "f"((a1.z + b1.z) * inv));
                uint32_t off = SWZ64(r * 64 + s * 16);
                asm volatile("st.shared.v4.b32 [%0], {%1,%2,%3,%4};"
                    :: "r"(smem_u32(buf + off)), "r"(p0), "r"(p1), "r"(p2), "r"(p3) : "memory");
            }
        }
        {
            int r = tid >> 2, s = tid & 3;
            uint32_t off = SWZ64(r * 64 + s * 16);
            CP_ASYNC16(smem_u32(buf + 16384 + off), Bh + (long long)(n0 + r) * K + k0 + s * 8);
            if (TERMS == 3)
                CP_ASYNC16(smem_u32(buf + 20480 + off), Bl + (long long)(n0 + r) * K + k0 + s * 8);
        }
    };

    copy_chunk(0); CP_COMMIT();
    copy_chunk(1); CP_COMMIT();

    float acc[2][4][4] = {};
    int NCk = K / 32;
    for (int ck = 0; ck < NCk; ck++) {
        CP_WAIT1();
        __syncthreads();
        uint32_t ab = smem_u32(sm + (ck & 1) * 24576);
        uint32_t bb = ab + 16384;
        #pragma unroll
        for (int s = 0; s < 2; s++) {
            int ko = s * 32;
            uint32_t ah[2][4], bh[2][4];
            ldm_x4(ah[0], lm64(ab, mw, ko, lane));
            ldm_x4(ah[1], lm64(ab, mw + 16, ko, lane));
            ldm_x4(bh[0], lm64(bb, nw, ko, lane));
            ldm_x4(bh[1], lm64(bb, nw + 16, ko, lane));
            if (TERMS == 3) {
                uint32_t al[2][4], bl[2][4];
                ldm_x4(al[0], lm64(ab + 8192, mw, ko, lane));
                ldm_x4(al[1], lm64(ab + 8192, mw + 16, ko, lane));
                ldm_x4(bl[0], lm64(bb + 4096, nw, ko, lane));
                ldm_x4(bl[1], lm64(bb + 4096, nw + 16, ko, lane));
                #pragma unroll
                for (int mt = 0; mt < 2; mt++) {
                    #pragma unroll
                    for (int ng = 0; ng < 2; ng++) {
                        mma16816(acc[mt][ng * 2],     ah[mt], bh[ng][0], bh[ng][2]);
                        mma16816(acc[mt][ng * 2 + 1], ah[mt], bh[ng][1], bh[ng][3]);
                        mma16816(acc[mt][ng * 2],     ah[mt], bl[ng][0], bl[ng][2]);
                        mma16816(acc[mt][ng * 2 + 1], ah[mt], bl[ng][1], bl[ng][3]);
                        mma16816(acc[mt][ng * 2],     al[mt], bh[ng][0], bh[ng][2]);
                        mma16816(acc[mt][ng * 2 + 1], al[mt], bh[ng][1], bh[ng][3]);
                    }
                }
            } else {
                #pragma unroll
                for (int mt = 0; mt < 2; mt++) {
                    #pragma unroll
                    for (int ng = 0; ng < 2; ng++) {
                        mma16816(acc[mt][ng * 2],     ah[mt], bh[ng][0], bh[ng][2]);
                        mma16816(acc[mt][ng * 2 + 1], ah[mt], bh[ng][1], bh[ng][3]);
                    }
                }
            }
        }
        __syncthreads();
        if (ck + 2 < NCk) copy_chunk(ck + 2);
        CP_COMMIT();
    }

    #pragma unroll
    for (int mt = 0; mt < 2; mt++) {
        #pragma unroll
        for (int nj = 0; nj < 4; nj++) {
            int r0 = m0 + mw + mt * 16 + (lane >> 2);
            int c0 = n0 + nw + nj * 8 + (lane & 3) * 2;
            float b0 = 0.f, b1 = 0.f;
            if (bias) { b0 = bias[c0]; b1 = bias[c0 + 1]; }
            float v0 = acc[mt][nj][0] + b0, v1 = acc[mt][nj][1] + b1;
            float v2 = acc[mt][nj][2] + b0, v3 = acc[mt][nj][3] + b1;
            if (EPI == 0) {
                *reinterpret_cast<float2*>(&C[(long long)r0 * N + c0]) = make_float2(v0, v1);
                *reinterpret_cast<float2*>(&C[(long long)(r0 + 8) * N + c0]) = make_float2(v2, v3);
            } else {
                int which = c0 >> 8;
                int hh = (c0 >> 6) & 3;
                int d = c0 & 63;
                __nv_bfloat16* dst = (which == 0) ? g_qbf : (which == 1) ? g_kbf : g_vbf;
                float scl = (which == 0) ? QS_CONST : 1.0f;
                *reinterpret_cast<__nv_bfloat162*>(dst + ((long long)hh * NN + r0) * 64 + d) =
                    __floats2bfloat162_rn(v0 * scl, v1 * scl);
                *reinterpret_cast<__nv_bfloat162*>(dst + ((long long)hh * NN + r0 + 8) * 64 + d) =
                    __floats2bfloat162_rn(v2 * scl, v3 * scl);
            }
        }
    }
}

// ---------------- warp-mma flash attention, split-K over 2 halves ----------------
__global__ void __launch_bounds__(128, 2) k_attn() {
    extern __shared__ char sm[];
    const int tid = threadIdx.x, w = tid >> 5, lane = tid & 31;
    const int h = blockIdx.y, qt = blockIdx.x, kvh = blockIdx.z;
    const int tile0 = kvh * 32;
    const uint32_t ONE2 = 0x3F803F80u;

    const __nv_bfloat16* ksrc0 = g_kbf + (long long)h * NN * 64;
    const __nv_bfloat16* vsrc0 = g_vbf + (long long)h * NN * 64;

    uint32_t qa[2][4][4];
    int qbase = qt * 128 + w * 32;
    #pragma unroll
    for (int r = 0; r < 2; r++) {
        const __nv_bfloat16* qb =
            g_qbf + ((long long)h * NN + qbase + r * 16 + (lane >> 2)) * 64 + (lane & 3) * 2;
        #pragma unroll
        for (int kk = 0; kk < 4; kk++) {
            qa[r][kk][0] = *reinterpret_cast<const uint32_t*>(qb + kk * 16);
            qa[r][kk][1] = *reinterpret_cast<const uint32_t*>(qb + 8 * 64 + kk * 16);
            qa[r][kk][2] = *reinterpret_cast<const uint32_t*>(qb + kk * 16 + 8);
            qa[r][kk][3] = *reinterpret_cast<const uint32_t*>(qb + 8 * 64 + kk * 16 + 8);
        }
    }

    auto copy_tile = [&](int gt) {
        const __nv_bfloat16* ks = ksrc0 + (long long)gt * 128 * 64;
        const __nv_bfloat16* vs = vsrc0 + (long long)gt * 128 * 64;
        char* kb = sm + (gt & 1) * 32768;
        char* vb = kb + 16384;
        #pragma unroll
        for (int i = 0; i < 8; i++) {
            int c = tid + i * 128;
            int row = c >> 3, seg = c & 7;
            uint32_t off = SWZ(row * 128 + seg * 16);
            CP_ASYNC16(smem_u32(kb + off), ks + row * 64 + seg * 8);
            CP_ASYNC16(smem_u32(vb + off), vs + row * 64 + seg * 8);
        }
    };

    copy_tile(tile0); CP_COMMIT();
    copy_tile(tile0 + 1); CP_COMMIT();

    float o[2][8][4] = {};
    float ol[2][4] = {};

    for (int t = 0; t < 32; t++) {
        int gt = tile0 + t;
        CP_WAIT1();
        __syncthreads();
        uint32_t kb0 = smem_u32(sm + (gt & 1) * 32768);

        #pragma unroll
        for (int half = 0; half < 2; half++) {
            uint32_t kbase = kb0 + half * 8192;
            uint32_t vbase = kb0 + 16384 + half * 8192;

            float sc[2][8][4] = {};
            #pragma unroll
            for (int kk = 0; kk < 4; kk++) {
                #pragma unroll
                for (int g = 0; g < 4; g++) {
                    uint32_t kr[4];
                    ldm_x4(kr, lm_addr(kbase, 16 * g, 32 * kk, lane));
                    #pragma unroll
                    for (int r = 0; r < 2; r++) {
                        mma16816(sc[r][2 * g],     qa[r][kk], kr[0], kr[2]);
                        mma16816(sc[r][2 * g + 1], qa[r][kk], kr[1], kr[3]);
                    }
                }
            }

            uint32_t pa[2][4][4];
            #pragma unroll
            for (int r = 0; r < 2; r++) {
                #pragma unroll
                for (int j = 0; j < 8; j++) {
                    #pragma unroll
                    for (int e = 0; e < 4; e++) {
                        float p;
                        asm("ex2.approx.ftz.f32 %0, %1;" : "=f"(p) : "f"(sc[r][j][e]));
                        sc[r][j][e] = p;
                    }
                }
                #pragma unroll
                for (int kk = 0; kk < 4; kk++) {
                    asm("cvt.rn.satfinite.bf16x2.f32 %0, %1, %2;" : "=r"(pa[r][kk][0]) : "f"(sc[r][2*kk][1]),   "f"(sc[r][2*kk][0]));
                    asm("cvt.rn.satfinite.bf16x2.f32 %0, %1, %2;" : "=r"(pa[r][kk][1]) : "f"(sc[r][2*kk][3]),   "f"(sc[r][2*kk][2]));
                    asm("cvt.rn.satfinite.bf16x2.f32 %0, %1, %2;" : "=r"(pa[r][kk][2]) : "f"(sc[r][2*kk+1][1]), "f"(sc[r][2*kk+1][0]));
                    asm("cvt.rn.satfinite.bf16x2.f32 %0, %1, %2;" : "=r"(pa[r][kk][3]) : "f"(sc[r][2*kk+1][3]), "f"(sc[r][2*kk+1][2]));
                }
                #pragma unroll
                for (int kk = 0; kk < 4; kk++)
                    mma16816(ol[r], pa[r][kk], ONE2, ONE2);
            }

            #pragma unroll
            for (int kk = 0; kk < 4; kk++) {
                #pragma unroll
                for (int gd = 0; gd < 4; gd++) {
                    uint32_t vr[4];
                    ldm_x4_t(vr, lm_addr(vbase, 16 * kk, 32 * gd, lane));
                    #pragma unroll
                    for (int r = 0; r < 2; r++) {
                        mma16816(o[r][2 * gd],     pa[r][kk], vr[0], vr[1]);
                        mma16816(o[r][2 * gd + 1], pa[r][kk], vr[2], vr[3]);
                    }
                }
            }
        }

        __syncthreads();
        if (t + 2 < 32) copy_tile(gt + 2);
        CP_COMMIT();
    }

    float* pO = g_pO + (long long)kvh * NN * CC;
    float* pl = g_pl + (long long)kvh * HH * NN + (long long)h * NN;
    #pragma unroll
    for (int r = 0; r < 2; r++) {
        int row = qbase + r * 16 + (lane >> 2);
        if ((lane & 3) == 0) {
            pl[row] = ol[r][0];
            pl[row + 8] = ol[r][2];
        }
        #pragma unroll
        for (int jj = 0; jj < 8; jj++) {
            long long idx = (long long)row * CC + h * 64 + jj * 8 + (lane & 3) * 2;
            *reinterpret_cast<float2*>(pO + idx) = make_float2(o[r][jj][0], o[r][jj][1]);
            *reinterpret_cast<float2*>(pO + idx + 8LL * CC) = make_float2(o[r][jj][2], o[r][jj][3]);
        }
    }
}

// ---------------- layernorm(x + proj) + combine -> split bf16 ----------------
__global__ void __launch_bounds__(256) k_lncomb(const float* __restrict__ x,
                                                const float* __restrict__ ln_g,
                                                const float* __restrict__ ln_b,
                                                const float* __restrict__ alpha) {
    int warp = threadIdx.x >> 5, lane = threadIdx.x & 31;
    int row = blockIdx.x * 8 + warp;
    const float* xp = x + (long long)row * CC;
    const float* pp = g_proj + (long long)row * CC;

    float2 v[4];
    float s = 0.f, sq = 0.f;
    #pragma unroll
    for (int k = 0; k < 4; k++) {
        int c = 2 * lane + k * 64;
        float t0 = xp[c] + pp[c];
        float t1 = xp[c + 1] + pp[c + 1];
        v[k] = make_float2(t0, t1);
        s += t0 + t1; sq += t0 * t0 + t1 * t1;
    }
    #pragma unroll
    for (int off = 16; off; off >>= 1) {
        s += __shfl_xor_sync(0xffffffffu, s, off);
        sq += __shfl_xor_sync(0xffffffffu, sq, off);
    }
    float mu = s * (1.f / 256.f);
    float var = sq * (1.f / 256.f) - mu * mu;
    float rstd = rsqrtf(var + 1e-5f);
    float w = 1.f / (1.f + expf(-alpha[0]));

    const float* lp = g_local + (long long)row * CC;
    #pragma unroll
    for (int k = 0; k < 4; k++) {
        int c = 2 * lane + k * 64;
        float ge0 = (v[k].x - mu) * rstd * ln_g[c] + ln_b[c];
        float ge1 = (v[k].y - mu) * rstd * ln_g[c + 1] + ln_b[c + 1];
        float c0 = w * lp[c] + (1.f - w) * ge0;
        float c1 = w * lp[c + 1] + (1.f - w) * ge1;
        store_split(g_ah, g_al, (long long)row * CC + c, c0, c1);
    }
}

extern "C" void kernel_launch(void* const* d_in, const int* in_sizes, int n_in,
                              void* d_out, int out_size) {
    const float* x        = (const float*)d_in[0];
    const int*   adj      = (const int*)d_in[1];
    const float* w_local  = (const float*)d_in[2];
    const float* in_w     = (const float*)d_in[3];
    const float* in_b     = (const float*)d_in[4];
    const float* out_w    = (const float*)d_in[5];
    const float* out_b    = (const float*)d_in[6];
    const float* ln_g     = (const float*)d_in[7];
    const float* ln_b     = (const float*)d_in[8];
    const float* alpha    = (const float*)d_in[9];
    const float* fc_w     = (const float*)d_in[10];
    const float* fc_b     = (const float*)d_in[11];
    float* out = (float*)d_out;

    void *p_proj_, *p_local_, *p_wh_, *p_wl_, *p_ah_, *p_al_, *p_bh_, *p_bl_;
    cudaGetSymbolAddress(&p_proj_, g_proj);
    cudaGetSymbolAddress(&p_local_, g_local);
    cudaGetSymbolAddress(&p_wh_, g_wh);
    cudaGetSymbolAddress(&p_wl_, g_wl);
    cudaGetSymbolAddress(&p_ah_, g_ah);
    cudaGetSymbolAddress(&p_al_, g_al);
    cudaGetSymbolAddress(&p_bh_, g_bh);
    cudaGetSymbolAddress(&p_bl_, g_bl);
    float* p_proj  = (float*)p_proj_;
    float* p_local = (float*)p_local_;
    const __nv_bfloat16* wh = (const __nv_bfloat16*)p_wh_;
    const __nv_bfloat16* wl = (const __nv_bfloat16*)p_wl_;
    const __nv_bfloat16* ah = (const __nv_bfloat16*)p_ah_;
    const __nv_bfloat16* al = (const __nv_bfloat16*)p_al_;
    const __nv_bfloat16* bh = (const __nv_bfloat16*)p_bh_;
    const __nv_bfloat16* bl = (const __nv_bfloat16*)p_bl_;

    static cudaStream_t s2 = nullptr, s3 = nullptr;
    static cudaEvent_t eFork = nullptr, eW = nullptr, eJoin = nullptr, eA = nullptr;
    if (!s2) {
        cudaFuncSetAttribute(k_attn, cudaFuncAttributeMaxDynamicSharedMemorySize, 65536);
        cudaStreamCreateWithFlags(&s2, cudaStreamNonBlocking);
        cudaStreamCreateWithFlags(&s3, cudaStreamNonBlocking);
        cudaEventCreateWithFlags(&eFork, cudaEventDisableTiming);
        cudaEventCreateWithFlags(&eW, cudaEventDisableTiming);
        cudaEventCreateWithFlags(&eJoin, cudaEventDisableTiming);
        cudaEventCreateWithFlags(&eA, cudaEventDisableTiming);
    }

    // ---- fork ----
    cudaEventRecord(eFork, 0);
    cudaStreamWaitEvent(s2, eFork, 0);
    cudaStreamWaitEvent(s3, eFork, 0);

    // s2: GCN chain
    k_zero<<<NN / 256, 256, 0, s2>>>();
    k_deg<<<EE / 256, 256, 0, s2>>>(adj);
    k_scan<<<1, 1024, 0, s2>>>();
    k_bin<<<EE / 256, 256, 0, s2>>>(adj);
    k_gather<<<NN / 4, 256, 0, s2>>>(x);

    // s3: split x -> g_ah/g_al (parallel with cvtw)
    k_cvta<<<NN * CC / 4 / 256, 256, 0, s3>>>(x);
    cudaEventRecord(eA, s3);

    // main: weights split
    k_cvtw<<<(1536 * 256) / 256, 256>>>(in_w, out_w, fc_w, w_local);
    cudaEventRecord(eW, 0);

    // s2: local = hi @ w_local — 3-term
    cudaStreamWaitEvent(s2, eW, 0);
    k_gemm_tc<0, 3, 0><<<dim3(4, 64), 256, 0, s2>>>(bh, bl, wh + 1280 * 256, wl + 1280 * 256,
                                                    nullptr, p_local, 256, 256);
    cudaEventRecord(eJoin, s2);

    // main: qkv = x @ in_w^T + in_b -> bf16 q/k/v  (1-term)
    cudaStreamWaitEvent(0, eA, 0);
    k_gemm_tc<1, 1, 0><<<dim3(12, 64), 256>>>(ah, al, wh, wl, in_b, nullptr, 768, 256);
    k_attn<<<dim3(NN / 128, HH, 2), 128, 65536>>>();
    // proj = combine(pO)/l @ out_w^T + out_b  (1-term, fused split-K combine)
    k_gemm_tc<0, 1, 1><<<dim3(4, 64), 256>>>(nullptr, nullptr, wh + 768 * 256, wl + 768 * 256,
                                             out_b, p_proj, 256, 256);

    // join + tail
    cudaStreamWaitEvent(0, eJoin, 0);
    k_lncomb<<<NN / 8, 256>>>(x, ln_g, ln_b, alpha);
    // fc: final output — 3-term
    k_gemm_tc<0, 3, 0><<<dim3(4, 64), 256>>>(ah, al, wh + 1024 * 256, wl + 1024 * 256,
                                             fc_b, out, 256, 256);
}

// round 17
// speedup vs baseline: 1.0238x; 1.0238x over previous
#include <cuda_runtime.h>
#include <cuda_bf16.h>
#include <cstdint>

#define NN 8192
#define CC 256
#define EE 262144
#define HH 4

// ---- scratch (no allocation allowed -> __device__ globals) ----
__device__ int   g_cnt[NN];
__device__ int   g_off[NN + 1];
__device__ int   g_cur[NN];
__device__ int2  g_ebuf[EE];                     // {row, float_bits(val)} binned by col
__device__ float g_proj[NN * CC];
__device__ float g_local[NN * CC];
__device__ float g_pO[2 * NN * CC];              // split-K attention O partials (raw sums)
__device__ float g_pl[2 * HH * NN];              // split-K l partials
__device__ __nv_bfloat16 g_qbf[HH * NN * 64];    // pre-scaled by 0.125*log2(e)
__device__ __nv_bfloat16 g_kbf[HH * NN * 64];
__device__ __nv_bfloat16 g_vbf[HH * NN * 64];
__device__ __nv_bfloat16 g_ah[NN * CC];          // activation hi [M,K]
__device__ __nv_bfloat16 g_al[NN * CC];          // activation lo
__device__ __nv_bfloat16 g_bh[NN * CC];          // GCN-path activation hi
__device__ __nv_bfloat16 g_bl[NN * CC];          // GCN-path activation lo
__device__ __nv_bfloat16 g_wh[1536 * CC];        // in_w(768)|out_w(256)|fc_w(256)|w_localT(256)
__device__ __nv_bfloat16 g_wl[1536 * CC];

#define QS_CONST (0.125f * 1.44269504089f)

// ================= helpers =================
__device__ __forceinline__ uint32_t smem_u32(const void* p) {
    uint32_t a;
    asm("{ .reg .u64 t; cvta.to.shared.u64 t, %1; cvt.u32.u64 %0, t; }" : "=r"(a) : "l"(p));
    return a;
}
#define SWZ(o)   ((o) ^ (((o) >> 3) & 0x70))
#define SWZ64(o) ((o) ^ (((o) >> 3) & 0x30))

#define CP_ASYNC16(dst, src) asm volatile("cp.async.cg.shared.global [%0], [%1], 16;" :: "r"(dst), "l"(src))
#define CP_COMMIT()          asm volatile("cp.async.commit_group;" ::: "memory")
#define CP_WAIT1()           asm volatile("cp.async.wait_group 1;" ::: "memory")

__device__ __forceinline__ void ldm_x4(uint32_t* r, uint32_t addr) {
    asm volatile("ldmatrix.sync.aligned.m8n8.x4.shared.b16 {%0,%1,%2,%3}, [%4];"
        : "=r"(r[0]), "=r"(r[1]), "=r"(r[2]), "=r"(r[3]) : "r"(addr));
}
__device__ __forceinline__ void ldm_x4_t(uint32_t* r, uint32_t addr) {
    asm volatile("ldmatrix.sync.aligned.m8n8.x4.trans.shared.b16 {%0,%1,%2,%3}, [%4];"
        : "=r"(r[0]), "=r"(r[1]), "=r"(r[2]), "=r"(r[3]) : "r"(addr));
}
__device__ __forceinline__ void mma16816(float* c, const uint32_t* a, uint32_t b0, uint32_t b1) {
    asm volatile("mma.sync.aligned.m16n8k16.row.col.f32.bf16.bf16.f32 "
        "{%0,%1,%2,%3}, {%4,%5,%6,%7}, {%8,%9}, {%0,%1,%2,%3};"
        : "+f"(c[0]), "+f"(c[1]), "+f"(c[2]), "+f"(c[3])
        : "r"(a[0]), "r"(a[1]), "r"(a[2]), "r"(a[3]), "r"(b0), "r"(b1));
}
__device__ __forceinline__ uint32_t lm_addr(uint32_t base, int row0, int off0, int lane) {
    int m = lane >> 3;
    int row = row0 + (lane & 7) + ((m & 1) << 3);
    int off = off0 + ((m >> 1) << 4);
    return base + SWZ(row * 128 + off);
}
__device__ __forceinline__ uint32_t lm64(uint32_t base, int row0, int off0, int lane) {
    int m = lane >> 3;
    int row = row0 + (lane & 7) + ((m & 1) << 3);
    int off = off0 + ((m >> 1) << 4);
    return base + SWZ64(row * 64 + off);
}
__device__ __forceinline__ void store_split(__nv_bfloat16* ah, __nv_bfloat16* al,
                                            long long idx, float v0, float v1) {
    __nv_bfloat16 h0 = __float2bfloat16(v0), h1 = __float2bfloat16(v1);
    *reinterpret_cast<__nv_bfloat162*>(ah + idx) = __nv_bfloat162(h0, h1);
    *reinterpret_cast<__nv_bfloat162*>(al + idx) =
        __floats2bfloat162_rn(v0 - __bfloat162float(h0), v1 - __bfloat162float(h1));
}

// ---------------- GCN: deg / scan / bin / gather ----------------
__global__ void k_zero() {
    int i = blockIdx.x * blockDim.x + threadIdx.x;
    if (i < NN) g_cnt[i] = 0;
}

__global__ void k_deg(const int* __restrict__ adj) {
    int e = blockIdx.x * blockDim.x + threadIdx.x;
    if (e >= EE) return;
    unsigned col = (unsigned)adj[EE + e];
    if (col < NN) atomicAdd(&g_cnt[col], 1);
}

// single block, 1024 threads, 8 elems/thread; warp scan + cross-warp
__global__ void __launch_bounds__(1024) k_scan() {
    __shared__ int wsum[32];
    int t = threadIdx.x, lane = t & 31, w = t >> 5;
    int4 a = reinterpret_cast<const int4*>(g_cnt)[2 * t];
    int4 b = reinterpret_cast<const int4*>(g_cnt)[2 * t + 1];
    int v[8] = {a.x, a.y, a.z, a.w, b.x, b.y, b.z, b.w};
    int pre[8], s = 0;
    #pragma unroll
    for (int i = 0; i < 8; i++) { pre[i] = s; s += v[i]; }
    int inc = s;
    #pragma unroll
    for (int off = 1; off < 32; off <<= 1) {
        int n = __shfl_up_sync(0xffffffffu, inc, off);
        if (lane >= off) inc += n;
    }
    if (lane == 31) wsum[w] = inc;
    __syncthreads();
    if (w == 0) {
        int x = wsum[lane];
        #pragma unroll
        for (int off = 1; off < 32; off <<= 1) {
            int n = __shfl_up_sync(0xffffffffu, x, off);
            if (lane >= off) x += n;
        }
        wsum[lane] = x;
    }
    __syncthreads();
    int base = (w ? wsum[w - 1] : 0) + inc - s;
    int o[8];
    #pragma unroll
    for (int i = 0; i < 8; i++) o[i] = base + pre[i];
    reinterpret_cast<int4*>(g_off)[2 * t]     = make_int4(o[0], o[1], o[2], o[3]);
    reinterpret_cast<int4*>(g_off)[2 * t + 1] = make_int4(o[4], o[5], o[6], o[7]);
    reinterpret_cast<int4*>(g_cur)[2 * t]     = make_int4(o[0], o[1], o[2], o[3]);
    reinterpret_cast<int4*>(g_cur)[2 * t + 1] = make_int4(o[4], o[5], o[6], o[7]);
    if (t == 1023) g_off[NN] = base + s;
}

__global__ void k_bin(const int* __restrict__ adj) {
    int e = blockIdx.x * blockDim.x + threadIdx.x;
    if (e >= EE) return;
    unsigned row = (unsigned)adj[e];
    unsigned col = (unsigned)adj[EE + e];
    if (row >= NN || col >= NN) return;
    float p = (float)(g_cnt[col] * g_cnt[row]);
    float val = (p > 0.f) ? rsqrtf(p) : 0.f;
    int pos = atomicAdd(&g_cur[col], 1);
    g_ebuf[pos] = make_int2((int)row, __float_as_int(val));
}

// 4 nodes per block; 64 threads/node, 4 channels/thread -> split-bf16 g_bh/g_bl
__global__ void __launch_bounds__(256) k_gather(const float* __restrict__ x) {
    int n = blockIdx.x * 4 + (threadIdx.x >> 6);
    int c = (threadIdx.x & 63) * 4;
    int e = g_off[n], end = g_off[n + 1];
    float a0 = 0.f, a1 = 0.f, a2 = 0.f, a3 = 0.f;
    for (; e + 2 <= end; e += 2) {
        int2 ev0 = g_ebuf[e], ev1 = g_ebuf[e + 1];
        float v0 = __int_as_float(ev0.y), v1 = __int_as_float(ev1.y);
        float4 x0 = *reinterpret_cast<const float4*>(x + (long long)ev0.x * CC + c);
        float4 x1 = *reinterpret_cast<const float4*>(x + (long long)ev1.x * CC + c);
        a0 += x0.x * v0 + x1.x * v1;
        a1 += x0.y * v0 + x1.y * v1;
        a2 += x0.z * v0 + x1.z * v1;
        a3 += x0.w * v0 + x1.w * v1;
    }
    if (e < end) {
        int2 ev = g_ebuf[e];
        float v = __int_as_float(ev.y);
        float4 x0 = *reinterpret_cast<const float4*>(x + (long long)ev.x * CC + c);
        a0 += x0.x * v; a1 += x0.y * v; a2 += x0.z * v; a3 += x0.w * v;
    }
    long long idx = (long long)n * CC + c;
    store_split(g_bh, g_bl, idx, a0, a1);
    store_split(g_bh, g_bl, idx + 2, a2, a3);
}

// ---------------- split-bf16 weight / activation conversion ----------------
__global__ void __launch_bounds__(256) k_cvtw(
    const float* __restrict__ in_w, const float* __restrict__ out_w,
    const float* __restrict__ fc_w, const float* __restrict__ w_local)
{
    int i = blockIdx.x * 256 + threadIdx.x;
    if (i >= 1536 * 256) return;
    int row = i >> 8, k = i & 255;
    float v;
    if (row < 768)       v = in_w[i];
    else if (row < 1024) v = out_w[(row - 768) * 256 + k];
    else if (row < 1280) v = fc_w[(row - 1024) * 256 + k];
    else                 v = w_local[k * 256 + (row - 1280)];   // transpose
    __nv_bfloat16 h = __float2bfloat16(v);
    g_wh[i] = h;
    g_wl[i] = __float2bfloat16(v - __bfloat162float(h));
}

__global__ void __launch_bounds__(256) k_cvta(const float* __restrict__ src) {
    int t = blockIdx.x * 256 + threadIdx.x;
    float4 v = reinterpret_cast<const float4*>(src)[t];
    long long idx = (long long)t * 4;
    store_split(g_ah, g_al, idx, v.x, v.y);
    store_split(g_ah, g_al, idx + 2, v.z, v.w);
}

// ---------------- tensor-core bf16 GEMM ----------------
// EPI 0: fp32 C + bias.  EPI 1: bf16 qkv (q scaled) straight to g_qbf/kbf/vbf.
// TERMS 3: Ah*Bh + Ah*Bl + Al*Bh (B from pre-split g_wh/g_wl pointers).
// TERMS 1 + BSRC 1: B loaded from fp32 weights Bf (row-major [N,K]), converted in-loader.
// TERMS 1 + BSRC 0: B from bf16 Bh.
template <int EPI, int TERMS, int BSRC>
__global__ void __launch_bounds__(256, 2) k_gemm_tc(
    const __nv_bfloat16* __restrict__ Ah, const __nv_bfloat16* __restrict__ Al,
    const __nv_bfloat16* __restrict__ Bh, const __nv_bfloat16* __restrict__ Bl,
    const float* __restrict__ Bf,
    const float* __restrict__ bias, float* __restrict__ C, int N, int K)
{
    __shared__ __align__(128) char sm[49152];
    int tid = threadIdx.x, w = tid >> 5, lane = tid & 31;
    int n0 = blockIdx.x * 64, m0 = blockIdx.y * 128;
    int mw = (w >> 1) * 32, nw = (w & 1) * 32;

    auto copy_chunk = [&](int ck) {
        int k0 = ck * 32;
        char* buf = sm + (ck & 1) * 24576;
        #pragma unroll
        for (int i = 0; i < 2; i++) {
            int c = tid + i * 256;
            int r = c >> 2, s = c & 3;
            uint32_t off = SWZ64(r * 64 + s * 16);
            CP_ASYNC16(smem_u32(buf + off), Ah + (long long)(m0 + r) * K + k0 + s * 8);
            if (TERMS == 3)
                CP_ASYNC16(smem_u32(buf + 8192 + off), Al + (long long)(m0 + r) * K + k0 + s * 8);
        }
        {
            int r = tid >> 2, s = tid & 3;
            uint32_t off = SWZ64(r * 64 + s * 16);
            if (BSRC == 0) {
                CP_ASYNC16(smem_u32(buf + 16384 + off), Bh + (long long)(n0 + r) * K + k0 + s * 8);
                if (TERMS == 3)
                    CP_ASYNC16(smem_u32(buf + 20480 + off), Bl + (long long)(n0 + r) * K + k0 + s * 8);
            } else {
                const float* src = Bf + (long long)(n0 + r) * K + k0 + s * 8;
                float4 f0 = *reinterpret_cast<const float4*>(src);
                float4 f1 = *reinterpret_cast<const float4*>(src + 4);
                uint32_t p0, p1, p2, p3;
                asm("cvt.rn.satfinite.bf16x2.f32 %0, %1, %2;" : "=r"(p0) : "f"(f0.y), "f"(f0.x));
                asm("cvt.rn.satfinite.bf16x2.f32 %0, %1, %2;" : "=r"(p1) : "f"(f0.w), "f"(f0.z));
                asm("cvt.rn.satfinite.bf16x2.f32 %0, %1, %2;" : "=r"(p2) : "f"(f1.y), "f"(f1.x));
                asm("cvt.rn.satfinite.bf16x2.f32 %0, %1, %2;" : "=r"(p3) : "f"(f1.w), "f"(f1.z));
                asm volatile("st.shared.v4.b32 [%0], {%1,%2,%3,%4};"
                    :: "r"(smem_u32(buf + 16384 + off)), "r"(p0), "r"(p1), "r"(p2), "r"(p3) : "memory");
            }
        }
    };

    copy_chunk(0); CP_COMMIT();
    copy_chunk(1); CP_COMMIT();

    float acc[2][4][4] = {};
    int NCk = K / 32;
    for (int ck = 0; ck < NCk; ck++) {
        CP_WAIT1();
        __syncthreads();
        uint32_t ab = smem_u32(sm + (ck & 1) * 24576);
        uint32_t bb = ab + 16384;
        #pragma unroll
        for (int s = 0; s < 2; s++) {
            int ko = s * 32;
            uint32_t ah[2][4], bh[2][4];
            ldm_x4(ah[0], lm64(ab, mw, ko, lane));
            ldm_x4(ah[1], lm64(ab, mw + 16, ko, lane));
            ldm_x4(bh[0], lm64(bb, nw, ko, lane));
            ldm_x4(bh[1], lm64(bb, nw + 16, ko, lane));
            if (TERMS == 3) {
                uint32_t al[2][4], bl[2][4];
                ldm_x4(al[0], lm64(ab + 8192, mw, ko, lane));
                ldm_x4(al[1], lm64(ab + 8192, mw + 16, ko, lane));
                ldm_x4(bl[0], lm64(bb + 4096, nw, ko, lane));
                ldm_x4(bl[1], lm64(bb + 4096, nw + 16, ko, lane));
                #pragma unroll
                for (int mt = 0; mt < 2; mt++) {
                    #pragma unroll
                    for (int ng = 0; ng < 2; ng++) {
                        mma16816(acc[mt][ng * 2],     ah[mt], bh[ng][0], bh[ng][2]);
                        mma16816(acc[mt][ng * 2 + 1], ah[mt], bh[ng][1], bh[ng][3]);
                        mma16816(acc[mt][ng * 2],     ah[mt], bl[ng][0], bl[ng][2]);
                        mma16816(acc[mt][ng * 2 + 1], ah[mt], bl[ng][1], bl[ng][3]);
                        mma16816(acc[mt][ng * 2],     al[mt], bh[ng][0], bh[ng][2]);
                        mma16816(acc[mt][ng * 2 + 1], al[mt], bh[ng][1], bh[ng][3]);
                    }
                }
            } else {
                #pragma unroll
                for (int mt = 0; mt < 2; mt++) {
                    #pragma unroll
                    for (int ng = 0; ng < 2; ng++) {
                        mma16816(acc[mt][ng * 2],     ah[mt], bh[ng][0], bh[ng][2]);
                        mma16816(acc[mt][ng * 2 + 1], ah[mt], bh[ng][1], bh[ng][3]);
                    }
                }
            }
        }
        __syncthreads();
        if (ck + 2 < NCk) copy_chunk(ck + 2);
        CP_COMMIT();
    }

    #pragma unroll
    for (int mt = 0; mt < 2; mt++) {
        #pragma unroll
        for (int nj = 0; nj < 4; nj++) {
            int r0 = m0 + mw + mt * 16 + (lane >> 2);
            int c0 = n0 + nw + nj * 8 + (lane & 3) * 2;
            float b0 = 0.f, b1 = 0.f;
            if (bias) { b0 = bias[c0]; b1 = bias[c0 + 1]; }
            float v0 = acc[mt][nj][0] + b0, v1 = acc[mt][nj][1] + b1;
            float v2 = acc[mt][nj][2] + b0, v3 = acc[mt][nj][3] + b1;
            if (EPI == 0) {
                *reinterpret_cast<float2*>(&C[(long long)r0 * N + c0]) = make_float2(v0, v1);
                *reinterpret_cast<float2*>(&C[(long long)(r0 + 8) * N + c0]) = make_float2(v2, v3);
            } else {
                int which = c0 >> 8;
                int hh = (c0 >> 6) & 3;
                int d = c0 & 63;
                __nv_bfloat16* dst = (which == 0) ? g_qbf : (which == 1) ? g_kbf : g_vbf;
                float scl = (which == 0) ? QS_CONST : 1.0f;
                *reinterpret_cast<__nv_bfloat162*>(dst + ((long long)hh * NN + r0) * 64 + d) =
                    __floats2bfloat162_rn(v0 * scl, v1 * scl);
                *reinterpret_cast<__nv_bfloat162*>(dst + ((long long)hh * NN + r0 + 8) * 64 + d) =
                    __floats2bfloat162_rn(v2 * scl, v3 * scl);
            }
        }
    }
}

// ---------------- warp-mma flash attention, split-K over 2 halves ----------------
__global__ void __launch_bounds__(128, 2) k_attn() {
    extern __shared__ char sm[];
    const int tid = threadIdx.x, w = tid >> 5, lane = tid & 31;
    const int h = blockIdx.y, qt = blockIdx.x, kvh = blockIdx.z;
    const int tile0 = kvh * 32;
    const uint32_t ONE2 = 0x3F803F80u;

    const __nv_bfloat16* ksrc0 = g_kbf + (long long)h * NN * 64;
    const __nv_bfloat16* vsrc0 = g_vbf + (long long)h * NN * 64;

    uint32_t qa[2][4][4];
    int qbase = qt * 128 + w * 32;
    #pragma unroll
    for (int r = 0; r < 2; r++) {
        const __nv_bfloat16* qb =
            g_qbf + ((long long)h * NN + qbase + r * 16 + (lane >> 2)) * 64 + (lane & 3) * 2;
        #pragma unroll
        for (int kk = 0; kk < 4; kk++) {
            qa[r][kk][0] = *reinterpret_cast<const uint32_t*>(qb + kk * 16);
            qa[r][kk][1] = *reinterpret_cast<const uint32_t*>(qb + 8 * 64 + kk * 16);
            qa[r][kk][2] = *reinterpret_cast<const uint32_t*>(qb + kk * 16 + 8);
            qa[r][kk][3] = *reinterpret_cast<const uint32_t*>(qb + 8 * 64 + kk * 16 + 8);
        }
    }

    auto copy_tile = [&](int gt) {
        const __nv_bfloat16* ks = ksrc0 + (long long)gt * 128 * 64;
        const __nv_bfloat16* vs = vsrc0 + (long long)gt * 128 * 64;
        char* kb = sm + (gt & 1) * 32768;
        char* vb = kb + 16384;
        #pragma unroll
        for (int i = 0; i < 8; i++) {
            int c = tid + i * 128;
            int row = c >> 3, seg = c & 7;
            uint32_t off = SWZ(row * 128 + seg * 16);
            CP_ASYNC16(smem_u32(kb + off), ks + row * 64 + seg * 8);
            CP_ASYNC16(smem_u32(vb + off), vs + row * 64 + seg * 8);
        }
    };

    copy_tile(tile0); CP_COMMIT();
    copy_tile(tile0 + 1); CP_COMMIT();

    float o[2][8][4] = {};
    float ol[2][4] = {};

    for (int t = 0; t < 32; t++) {
        int gt = tile0 + t;
        CP_WAIT1();
        __syncthreads();
        uint32_t kb0 = smem_u32(sm + (gt & 1) * 32768);

        #pragma unroll
        for (int half = 0; half < 2; half++) {
            uint32_t kbase = kb0 + half * 8192;
            uint32_t vbase = kb0 + 16384 + half * 8192;

            float sc[2][8][4] = {};
            #pragma unroll
            for (int kk = 0; kk < 4; kk++) {
                #pragma unroll
                for (int g = 0; g < 4; g++) {
                    uint32_t kr[4];
                    ldm_x4(kr, lm_addr(kbase, 16 * g, 32 * kk, lane));
                    #pragma unroll
                    for (int r = 0; r < 2; r++) {
                        mma16816(sc[r][2 * g],     qa[r][kk], kr[0], kr[2]);
                        mma16816(sc[r][2 * g + 1], qa[r][kk], kr[1], kr[3]);
                    }
                }
            }

            uint32_t pa[2][4][4];
            #pragma unroll
            for (int r = 0; r < 2; r++) {
                #pragma unroll
                for (int j = 0; j < 8; j++) {
                    #pragma unroll
                    for (int e = 0; e < 4; e++) {
                        float p;
                        asm("ex2.approx.ftz.f32 %0, %1;" : "=f"(p) : "f"(sc[r][j][e]));
                        sc[r][j][e] = p;
                    }
                }
                #pragma unroll
                for (int kk = 0; kk < 4; kk++) {
                    asm("cvt.rn.satfinite.bf16x2.f32 %0, %1, %2;" : "=r"(pa[r][kk][0]) : "f"(sc[r][2*kk][1]),   "f"(sc[r][2*kk][0]));
                    asm("cvt.rn.satfinite.bf16x2.f32 %0, %1, %2;" : "=r"(pa[r][kk][1]) : "f"(sc[r][2*kk][3]),   "f"(sc[r][2*kk][2]));
                    asm("cvt.rn.satfinite.bf16x2.f32 %0, %1, %2;" : "=r"(pa[r][kk][2]) : "f"(sc[r][2*kk+1][1]), "f"(sc[r][2*kk+1][0]));
                    asm("cvt.rn.satfinite.bf16x2.f32 %0, %1, %2;" : "=r"(pa[r][kk][3]) : "f"(sc[r][2*kk+1][3]), "f"(sc[r][2*kk+1][2]));
                }
                #pragma unroll
                for (int kk = 0; kk < 4; kk++)
                    mma16816(ol[r], pa[r][kk], ONE2, ONE2);
            }

            #pragma unroll
            for (int kk = 0; kk < 4; kk++) {
                #pragma unroll
                for (int gd = 0; gd < 4; gd++) {
                    uint32_t vr[4];
                    ldm_x4_t(vr, lm_addr(vbase, 16 * kk, 32 * gd, lane));
                    #pragma unroll
                    for (int r = 0; r < 2; r++) {
                        mma16816(o[r][2 * gd],     pa[r][kk], vr[0], vr[1]);
                        mma16816(o[r][2 * gd + 1], pa[r][kk], vr[2], vr[3]);
                    }
                }
            }
        }

        __syncthreads();
        if (t + 2 < 32) copy_tile(gt + 2);
        CP_COMMIT();
    }

    float* pO = g_pO + (long long)kvh * NN * CC;
    float* pl = g_pl + (long long)kvh * HH * NN + (long long)h * NN;
    #pragma unroll
    for (int r = 0; r < 2; r++) {
        int row = qbase + r * 16 + (lane >> 2);
        if ((lane & 3) == 0) {
            pl[row] = ol[r][0];
            pl[row + 8] = ol[r][2];
        }
        #pragma unroll
        for (int jj = 0; jj < 8; jj++) {
            long long idx = (long long)row * CC + h * 64 + jj * 8 + (lane & 3) * 2;
            *reinterpret_cast<float2*>(pO + idx) = make_float2(o[r][jj][0], o[r][jj][1]);
            *reinterpret_cast<float2*>(pO + idx + 8LL * CC) = make_float2(o[r][jj][2], o[r][jj][3]);
        }
    }
}

// ---------------- split-K combine: (O0+O1)/(l0+l1) -> bf16 (proj GEMM is 1-term) ----------------
__global__ void __launch_bounds__(256) k_comb() {
    int t = blockIdx.x * 256 + threadIdx.x;
    int c4 = (t & 63) * 4;
    int row = t >> 6;
    int h = c4 >> 6;
    float l = g_pl[h * NN + row] + g_pl[HH * NN + h * NN + row];
    float inv = 1.0f / l;
    long long idx = (long long)row * CC + c4;
    float4 a = *reinterpret_cast<const float4*>(g_pO + idx);
    float4 b = *reinterpret_cast<const float4*>(g_pO + (long long)NN * CC + idx);
    __nv_bfloat162* d = reinterpret_cast<__nv_bfloat162*>(g_ah + idx);
    d[0] = __floats2bfloat162_rn((a.x + b.x) * inv, (a.y + b.y) * inv);
    d[1] = __floats2bfloat162_rn((a.z + b.z) * inv, (a.w + b.w) * inv);
}

// ---------------- layernorm(x + proj) + combine -> split bf16 ----------------
__global__ void __launch_bounds__(256) k_lncomb(const float* __restrict__ x,
                                                const float* __restrict__ ln_g,
                                                const float* __restrict__ ln_b,
                                                const float* __restrict__ alpha) {
    int warp = threadIdx.x >> 5, lane = threadIdx.x & 31;
    int row = blockIdx.x * 8 + warp;
    const float* xp = x + (long long)row * CC;
    const float* pp = g_proj + (long long)row * CC;

    float2 v[4];
    float s = 0.f, sq = 0.f;
    #pragma unroll
    for (int k = 0; k < 4; k++) {
        int c = 2 * lane + k * 64;
        float t0 = xp[c] + pp[c];
        float t1 = xp[c + 1] + pp[c + 1];
        v[k] = make_float2(t0, t1);
        s += t0 + t1; sq += t0 * t0 + t1 * t1;
    }
    #pragma unroll
    for (int off = 16; off; off >>= 1) {
        s += __shfl_xor_sync(0xffffffffu, s, off);
        sq += __shfl_xor_sync(0xffffffffu, sq, off);
    }
    float mu = s * (1.f / 256.f);
    float var = sq * (1.f / 256.f) - mu * mu;
    float rstd = rsqrtf(var + 1e-5f);
    float w = 1.f / (1.f + expf(-alpha[0]));

    const float* lp = g_local + (long long)row * CC;
    #pragma unroll
    for (int k = 0; k < 4; k++) {
        int c = 2 * lane + k * 64;
        float ge0 = (v[k].x - mu) * rstd * ln_g[c] + ln_b[c];
        float ge1 = (v[k].y - mu) * rstd * ln_g[c + 1] + ln_b[c + 1];
        float c0 = w * lp[c] + (1.f - w) * ge0;
        float c1 = w * lp[c + 1] + (1.f - w) * ge1;
        store_split(g_ah, g_al, (long long)row * CC + c, c0, c1);
    }
}

extern "C" void kernel_launch(void* const* d_in, const int* in_sizes, int n_in,
                              void* d_out, int out_size) {
    const float* x        = (const float*)d_in[0];
    const int*   adj      = (const int*)d_in[1];
    const float* w_local  = (const float*)d_in[2];
    const float* in_w     = (const float*)d_in[3];
    const float* in_b     = (const float*)d_in[4];
    const float* out_w    = (const float*)d_in[5];
    const float* out_b    = (const float*)d_in[6];
    const float* ln_g     = (const float*)d_in[7];
    const float* ln_b     = (const float*)d_in[8];
    const float* alpha    = (const float*)d_in[9];
    const float* fc_w     = (const float*)d_in[10];
    const float* fc_b     = (const float*)d_in[11];
    float* out = (float*)d_out;

    void *p_proj_, *p_local_, *p_wh_, *p_wl_, *p_ah_, *p_al_, *p_bh_, *p_bl_;
    cudaGetSymbolAddress(&p_proj_, g_proj);
    cudaGetSymbolAddress(&p_local_, g_local);
    cudaGetSymbolAddress(&p_wh_, g_wh);
    cudaGetSymbolAddress(&p_wl_, g_wl);
    cudaGetSymbolAddress(&p_ah_, g_ah);
    cudaGetSymbolAddress(&p_al_, g_al);
    cudaGetSymbolAddress(&p_bh_, g_bh);
    cudaGetSymbolAddress(&p_bl_, g_bl);
    float* p_proj  = (float*)p_proj_;
    float* p_local = (float*)p_local_;
    const __nv_bfloat16* wh = (const __nv_bfloat16*)p_wh_;
    const __nv_bfloat16* wl = (const __nv_bfloat16*)p_wl_;
    const __nv_bfloat16* ah = (const __nv_bfloat16*)p_ah_;
    const __nv_bfloat16* al = (const __nv_bfloat16*)p_al_;
    const __nv_bfloat16* bh = (const __nv_bfloat16*)p_bh_;
    const __nv_bfloat16* bl = (const __nv_bfloat16*)p_bl_;

    static cudaStream_t s2 = nullptr, s3 = nullptr;
    static cudaEvent_t eFork = nullptr, eW = nullptr, eJoin = nullptr, eA = nullptr;
    if (!s2) {
        cudaFuncSetAttribute(k_attn, cudaFuncAttributeMaxDynamicSharedMemorySize, 65536);
        cudaStreamCreateWithFlags(&s2, cudaStreamNonBlocking);
        cudaStreamCreateWithFlags(&s3, cudaStreamNonBlocking);
        cudaEventCreateWithFlags(&eFork, cudaEventDisableTiming);
        cudaEventCreateWithFlags(&eW, cudaEventDisableTiming);
        cudaEventCreateWithFlags(&eJoin, cudaEventDisableTiming);
        cudaEventCreateWithFlags(&eA, cudaEventDisableTiming);
    }

    // ---- fork ----
    cudaEventRecord(eFork, 0);
    cudaStreamWaitEvent(s2, eFork, 0);
    cudaStreamWaitEvent(s3, eFork, 0);

    // s2: GCN chain
    k_zero<<<NN / 256, 256, 0, s2>>>();
    k_deg<<<EE / 256, 256, 0, s2>>>(adj);
    k_scan<<<1, 1024, 0, s2>>>();
    k_bin<<<EE / 256, 256, 0, s2>>>(adj);
    k_gather<<<NN / 4, 256, 0, s2>>>(x);

    // s3: split x (needed by qkv) then weights split (needed only by local + fc)
    k_cvta<<<NN * CC / 4 / 256, 256, 0, s3>>>(x);
    cudaEventRecord(eA, s3);
    k_cvtw<<<(1536 * 256) / 256, 256, 0, s3>>>(in_w, out_w, fc_w, w_local);
    cudaEventRecord(eW, s3);

    // s2: local = hi @ w_local — 3-term (waits split weights)
    cudaStreamWaitEvent(s2, eW, 0);
    k_gemm_tc<0, 3, 0><<<dim3(4, 64), 256, 0, s2>>>(bh, bl, wh + 1280 * 256, wl + 1280 * 256,
                                                    nullptr, nullptr, p_local, 256, 256);
    cudaEventRecord(eJoin, s2);

    // main: qkv = x @ in_w^T + in_b -> bf16 q/k/v  (1-term, B converted in-loader)
    cudaStreamWaitEvent(0, eA, 0);
    k_gemm_tc<1, 1, 1><<<dim3(12, 64), 256>>>(ah, al, nullptr, nullptr, in_w,
                                              in_b, nullptr, 768, 256);
    k_attn<<<dim3(NN / 128, HH, 2), 128, 65536>>>();
    k_comb<<<NN * CC / 4 / 256, 256>>>();
    // proj (1-term, B converted in-loader from fp32 out_w)
    k_gemm_tc<0, 1, 1><<<dim3(4, 64), 256>>>(ah, al, nullptr, nullptr, out_w,
                                             out_b, p_proj, 256, 256);

    // join + tail
    cudaStreamWaitEvent(0, eJoin, 0);
    k_lncomb<<<NN / 8, 256>>>(x, ln_g, ln_b, alpha);
    // fc: final output — 3-term (needs split weights)
    cudaStreamWaitEvent(0, eW, 0);
    k_gemm_tc<0, 3, 0><<<dim3(4, 64), 256>>>(ah, al, wh + 1024 * 256, wl + 1024 * 256,
                                             nullptr, fc_b, out, 256, 256);
}